// round 1
// baseline (speedup 1.0000x reference)
#include <cuda_runtime.h>
#include <cstdint>

// Problem shape (fixed by the reference setup_inputs)
#define L_LEN 4096
#define N_ROWS 4096
#define TPB 512
#define CHUNK (L_LEN / TPB)   // 8 timesteps per thread
#define NWARPS (TPB / 32)     // 16

// Numerically safe softplus: log(1+e^x) = max(x,0) + log1p(e^{-|x|})
__device__ __forceinline__ float softplus_f(float x) {
    return fmaxf(x, 0.0f) + log1pf(expf(-fabsf(x)));
}

__global__ __launch_bounds__(TPB)
void socnet_kernel(const float* __restrict__ X,
                   const float* __restrict__ SC,
                   const float* __restrict__ w_init1,
                   const float* __restrict__ b_init1,
                   const float* __restrict__ w_init2,
                   const float* __restrict__ b_init2,
                   const float* __restrict__ w_eta1,
                   const float* __restrict__ b_eta1,
                   const float* __restrict__ w_eta2,
                   const float* __restrict__ b_eta2,
                   float* __restrict__ out) {
    __shared__ float4 s_warp[NWARPS];
    __shared__ float  s_soc;

    const int row  = blockIdx.x;
    const int tid  = threadIdx.x;
    const int lane = tid & 31;
    const int warp = tid >> 5;

    const float4* __restrict__ Xr = reinterpret_cast<const float4*>(X) + (size_t)row * L_LEN;
    float4* __restrict__ Or       = reinterpret_cast<float4*>(out)     + (size_t)row * L_LEN;

    // Per-row scalars from SC: [Q, eta0, R, cap]
    const float Q    = SC[row * 4 + 0];
    const float eta0 = SC[row * 4 + 1];
    const float R    = SC[row * 4 + 2];
    const float cap  = SC[row * 4 + 3];

    // Tiny MLP weights (L2-resident scalars)
    const float we0 = w_eta1[0];
    const float we1 = w_eta1[1];
    const float be1 = b_eta1[0];
    const float we2 = w_eta2[0];
    const float be2 = b_eta2[0];

    const float dscale = eta0 / (3600.0f * Q);

    // soc_init = cap * (1 + mlp_init([I0, T0, U0, R]))
    if (tid == 0) {
        float4 x0 = Xr[0];
        float z = w_init1[0] * x0.y + w_init1[1] * x0.z
                + w_init1[2] * x0.w + w_init1[3] * R + b_init1[0];
        float h = softplus_f(z);
        s_soc = cap * (1.0f + (w_init2[0] * h + b_init2[0]));
    }

    const int t0 = tid * CHUNK;

    // State at timestep t0: v = (I, T, U, delta_eta), dy
    float4 x = Xr[t0];
    float I = x.y, T = x.z, U = x.w;
    float de = we2 * softplus_f(we0 * I + we1 * T + be1) + be2;
    float dy = dscale * (1.0f + de) * I;

    // Local inclusive prefix of increments inside this chunk
    float4 cum = make_float4(0.0f, 0.0f, 0.0f, 0.0f);
    float4 loc[CHUNK];
    #pragma unroll
    for (int k = 0; k < CHUNK; ++k) {
        const int tn = t0 + k + 1;
        float In, Tn, Un, den;
        if (tn < L_LEN) {
            float4 xn = Xr[tn];
            In = xn.y; Tn = xn.z; Un = xn.w;
            den = we2 * softplus_f(we0 * In + we1 * Tn + be1) + be2;
        } else {
            // Last increment (s = L-1) does not exist -> force inc = 0
            In = I; Tn = T; Un = U; den = de;
        }
        cum.x += dy * (In - I);
        cum.y += dy * (Tn - T);
        cum.z += dy * (Un - U);
        cum.w += dy * (den - de);
        loc[k] = cum;
        I = In; T = Tn; U = Un; de = den;
        dy = dscale * (1.0f + de) * I;
    }

    // ---- Block-wide exclusive scan of chunk totals (4 channels) ----
    const float4 tot = cum;

    // Warp inclusive scan
    float4 incl = tot;
    #pragma unroll
    for (int d = 1; d < 32; d <<= 1) {
        float ax = __shfl_up_sync(0xFFFFFFFFu, incl.x, d);
        float ay = __shfl_up_sync(0xFFFFFFFFu, incl.y, d);
        float az = __shfl_up_sync(0xFFFFFFFFu, incl.z, d);
        float aw = __shfl_up_sync(0xFFFFFFFFu, incl.w, d);
        if (lane >= d) { incl.x += ax; incl.y += ay; incl.z += az; incl.w += aw; }
    }
    if (lane == 31) s_warp[warp] = incl;
    __syncthreads();

    // Warp 0 scans the 16 warp totals -> exclusive warp offsets
    if (warp == 0) {
        float4 v = (lane < NWARPS) ? s_warp[lane] : make_float4(0.f, 0.f, 0.f, 0.f);
        #pragma unroll
        for (int d = 1; d < NWARPS; d <<= 1) {
            float ax = __shfl_up_sync(0xFFFFFFFFu, v.x, d);
            float ay = __shfl_up_sync(0xFFFFFFFFu, v.y, d);
            float az = __shfl_up_sync(0xFFFFFFFFu, v.z, d);
            float aw = __shfl_up_sync(0xFFFFFFFFu, v.w, d);
            if (lane >= d) { v.x += ax; v.y += ay; v.z += az; v.w += aw; }
        }
        float4 e;
        e.x = __shfl_up_sync(0xFFFFFFFFu, v.x, 1);
        e.y = __shfl_up_sync(0xFFFFFFFFu, v.y, 1);
        e.z = __shfl_up_sync(0xFFFFFFFFu, v.z, 1);
        e.w = __shfl_up_sync(0xFFFFFFFFu, v.w, 1);
        if (lane == 0) e = make_float4(0.f, 0.f, 0.f, 0.f);
        if (lane < NWARPS) s_warp[lane] = e;
    }
    __syncthreads();

    // Thread-exclusive offset = warp base + (shifted warp-inclusive)
    float4 wb = s_warp[warp];
    float4 te;
    te.x = __shfl_up_sync(0xFFFFFFFFu, incl.x, 1);
    te.y = __shfl_up_sync(0xFFFFFFFFu, incl.y, 1);
    te.z = __shfl_up_sync(0xFFFFFFFFu, incl.z, 1);
    te.w = __shfl_up_sync(0xFFFFFFFFu, incl.w, 1);
    if (lane == 0) te = make_float4(0.f, 0.f, 0.f, 0.f);

    const float soc = s_soc;
    const float bx = soc + wb.x + te.x;
    const float by = soc + wb.y + te.y;
    const float bz = soc + wb.z + te.z;
    const float bw = soc + wb.w + te.w;

    if (tid == 0) {
        Or[0] = make_float4(soc, soc, soc, soc);
    }

    #pragma unroll
    for (int k = 0; k < CHUNK; ++k) {
        const int ti = t0 + k + 1;
        if (ti < L_LEN) {
            float4 o;
            o.x = bx + loc[k].x;
            o.y = by + loc[k].y;
            o.z = bz + loc[k].z;
            o.w = bw + loc[k].w;
            Or[ti] = o;
        }
    }
}

extern "C" void kernel_launch(void* const* d_in, const int* in_sizes, int n_in,
                              void* d_out, int out_size) {
    const float* X       = (const float*)d_in[0];
    const float* SC      = (const float*)d_in[1];
    const float* w_init1 = (const float*)d_in[2];
    const float* b_init1 = (const float*)d_in[3];
    const float* w_init2 = (const float*)d_in[4];
    const float* b_init2 = (const float*)d_in[5];
    const float* w_eta1  = (const float*)d_in[6];
    const float* b_eta1  = (const float*)d_in[7];
    const float* w_eta2  = (const float*)d_in[8];
    const float* b_eta2  = (const float*)d_in[9];
    float* out = (float*)d_out;

    socnet_kernel<<<N_ROWS, TPB>>>(X, SC,
                                   w_init1, b_init1, w_init2, b_init2,
                                   w_eta1, b_eta1, w_eta2, b_eta2,
                                   out);
}

// round 2
// speedup vs baseline: 1.2120x; 1.2120x over previous
#include <cuda_runtime.h>
#include <cstdint>

#define L_LEN 4096
#define N_ROWS 4096
#define TPB 512
#define ROUNDS (L_LEN / TPB)   // 8
#define NWARPS (TPB / 32)      // 16

// Numerically safe softplus: log(1+e^x) = max(x,0) + log1p(e^{-|x|})
__device__ __forceinline__ float softplus_f(float x) {
    return fmaxf(x, 0.0f) + log1pf(expf(-fabsf(x)));
}

__global__ __launch_bounds__(TPB, 3)
void socnet_kernel(const float* __restrict__ X,
                   const float* __restrict__ SC,
                   const float* __restrict__ w_init1,
                   const float* __restrict__ b_init1,
                   const float* __restrict__ w_init2,
                   const float* __restrict__ b_init2,
                   const float* __restrict__ w_eta1,
                   const float* __restrict__ b_eta1,
                   const float* __restrict__ w_eta2,
                   const float* __restrict__ b_eta2,
                   float* __restrict__ out) {
    __shared__ float4 s_first[NWARPS];  // first element (I,T,U,de) of each warp's segment
    __shared__ float4 s_woff[NWARPS];   // warp totals -> exclusive warp offsets
    __shared__ float4 s_total;          // block total of this round
    __shared__ float  s_soc;

    const int row  = blockIdx.x;
    const int tid  = threadIdx.x;
    const int lane = tid & 31;
    const int warp = tid >> 5;

    const float4* __restrict__ Xr = reinterpret_cast<const float4*>(X) + (size_t)row * L_LEN;
    float4* __restrict__ Or       = reinterpret_cast<float4*>(out)     + (size_t)row * L_LEN;

    // Per-row scalars from SC: [Q, eta0, R, cap]
    const float Q    = SC[row * 4 + 0];
    const float eta0 = SC[row * 4 + 1];
    const float R    = SC[row * 4 + 2];
    const float cap  = SC[row * 4 + 3];

    const float we0 = w_eta1[0];
    const float we1 = w_eta1[1];
    const float be1 = b_eta1[0];
    const float we2 = w_eta2[0];
    const float be2 = b_eta2[0];

    const float dscale = eta0 / (3600.0f * Q);

    if (tid == 0) {
        float4 x0 = Xr[0];
        float z = w_init1[0] * x0.y + w_init1[1] * x0.z
                + w_init1[2] * x0.w + w_init1[3] * R + b_init1[0];
        float h = softplus_f(z);
        s_soc = cap * (1.0f + (w_init2[0] * h + b_init2[0]));
    }

    // Cross-round carry (prefix of all earlier rounds' increments)
    float cx = 0.f, cy = 0.f, cz = 0.f, cw = 0.f;
    float soc = 0.f;

    #pragma unroll 1
    for (int r = 0; r < ROUNDS; ++r) {
        const int t = r * TPB + tid;
        const bool last_elem = (t == L_LEN - 1);

        // Coalesced load of this thread's timestep
        float4 x = Xr[t];
        float I = x.y, T = x.z, U = x.w;
        float de = we2 * softplus_f(we0 * I + we1 * T + be1) + be2;

        if (lane == 0) s_first[warp] = make_float4(I, T, U, de);
        __syncthreads();                       // barrier A
        soc = s_soc;

        // Neighbor (t+1) values: shfl within warp, shared across warps,
        // direct load at the block/round boundary (1 thread).
        float In  = __shfl_down_sync(0xFFFFFFFFu, I, 1);
        float Tn  = __shfl_down_sync(0xFFFFFFFFu, T, 1);
        float Un  = __shfl_down_sync(0xFFFFFFFFu, U, 1);
        float den = __shfl_down_sync(0xFFFFFFFFu, de, 1);
        if (lane == 31) {
            if (warp < NWARPS - 1) {
                float4 f = s_first[warp + 1];
                In = f.x; Tn = f.y; Un = f.z; den = f.w;
            } else if (!last_elem) {
                float4 xn = Xr[t + 1];
                In = xn.y; Tn = xn.z; Un = xn.w;
                den = we2 * softplus_f(we0 * In + we1 * Tn + be1) + be2;
            }
        }

        const float dy = dscale * (1.0f + de) * I;
        float ix, iy, iz, iw;
        if (last_elem) {
            ix = iy = iz = iw = 0.f;           // inc[L-1] does not exist
        } else {
            ix = dy * (In - I);
            iy = dy * (Tn - T);
            iz = dy * (Un - U);
            iw = dy * (den - de);
        }

        // Warp-inclusive scan (4 channels)
        float sx = ix, sy = iy, sz = iz, sw = iw;
        #pragma unroll
        for (int d = 1; d < 32; d <<= 1) {
            float ax = __shfl_up_sync(0xFFFFFFFFu, sx, d);
            float ay = __shfl_up_sync(0xFFFFFFFFu, sy, d);
            float az = __shfl_up_sync(0xFFFFFFFFu, sz, d);
            float aw = __shfl_up_sync(0xFFFFFFFFu, sw, d);
            if (lane >= d) { sx += ax; sy += ay; sz += az; sw += aw; }
        }
        if (lane == 31) s_woff[warp] = make_float4(sx, sy, sz, sw);
        __syncthreads();                       // barrier B

        if (warp == 0) {
            float4 v = (lane < NWARPS) ? s_woff[lane]
                                       : make_float4(0.f, 0.f, 0.f, 0.f);
            #pragma unroll
            for (int d = 1; d < NWARPS; d <<= 1) {
                float ax = __shfl_up_sync(0xFFFFFFFFu, v.x, d);
                float ay = __shfl_up_sync(0xFFFFFFFFu, v.y, d);
                float az = __shfl_up_sync(0xFFFFFFFFu, v.z, d);
                float aw = __shfl_up_sync(0xFFFFFFFFu, v.w, d);
                if (lane >= d) { v.x += ax; v.y += ay; v.z += az; v.w += aw; }
            }
            float4 e;
            e.x = __shfl_up_sync(0xFFFFFFFFu, v.x, 1);
            e.y = __shfl_up_sync(0xFFFFFFFFu, v.y, 1);
            e.z = __shfl_up_sync(0xFFFFFFFFu, v.z, 1);
            e.w = __shfl_up_sync(0xFFFFFFFFu, v.w, 1);
            if (lane == 0) e = make_float4(0.f, 0.f, 0.f, 0.f);
            if (lane == NWARPS - 1) s_total = v;   // block total this round
            if (lane < NWARPS) s_woff[lane] = e;   // exclusive warp offsets
        }
        __syncthreads();                       // barrier C

        // Thread-exclusive prefix = warp offset + shifted warp-inclusive
        float4 wb = s_woff[warp];
        float ex = __shfl_up_sync(0xFFFFFFFFu, sx, 1);
        float ey = __shfl_up_sync(0xFFFFFFFFu, sy, 1);
        float ez = __shfl_up_sync(0xFFFFFFFFu, sz, 1);
        float ew = __shfl_up_sync(0xFFFFFFFFu, sw, 1);
        if (lane == 0) { ex = ey = ez = ew = 0.f; }

        float4 o;
        o.x = soc + cx + wb.x + ex;
        o.y = soc + cy + wb.y + ey;
        o.z = soc + cz + wb.z + ez;
        o.w = soc + cw + wb.w + ew;
        Or[t] = o;                             // coalesced store

        float4 bt = s_total;
        cx += bt.x; cy += bt.y; cz += bt.z; cw += bt.w;
    }
}

extern "C" void kernel_launch(void* const* d_in, const int* in_sizes, int n_in,
                              void* d_out, int out_size) {
    const float* X       = (const float*)d_in[0];
    const float* SC      = (const float*)d_in[1];
    const float* w_init1 = (const float*)d_in[2];
    const float* b_init1 = (const float*)d_in[3];
    const float* w_init2 = (const float*)d_in[4];
    const float* b_init2 = (const float*)d_in[5];
    const float* w_eta1  = (const float*)d_in[6];
    const float* b_eta1  = (const float*)d_in[7];
    const float* w_eta2  = (const float*)d_in[8];
    const float* b_eta2  = (const float*)d_in[9];
    float* out = (float*)d_out;

    socnet_kernel<<<N_ROWS, TPB>>>(X, SC,
                                   w_init1, b_init1, w_init2, b_init2,
                                   w_eta1, b_eta1, w_eta2, b_eta2,
                                   out);
}

// round 3
// speedup vs baseline: 1.7228x; 1.4215x over previous
#include <cuda_runtime.h>

#define L_LEN 4096
#define N_ROWS 4096
#define TPB 512
#define ROUNDS 2
#define SEG (L_LEN / ROUNDS)     // 2048 timesteps per round
#define CHUNK (SEG / TPB)        // 4 consecutive timesteps per thread
#define NWARPS (TPB / 32)        // 16
#define SMEM_F4 (SEG + SEG / 4)  // 2560 float4 = 40 KB (pad 1 slot per 4)

// Fast, numerically safe softplus: max(x,0) + log(1 + e^{-|x|})
__device__ __forceinline__ float softplus_f(float x) {
    return fmaxf(x, 0.0f) + __logf(1.0f + __expf(-fabsf(x)));
}

__global__ __launch_bounds__(TPB, 2)
void socnet_kernel(const float* __restrict__ X,
                   const float* __restrict__ SC,
                   const float* __restrict__ w_init1,
                   const float* __restrict__ b_init1,
                   const float* __restrict__ w_init2,
                   const float* __restrict__ b_init2,
                   const float* __restrict__ w_eta1,
                   const float* __restrict__ b_eta1,
                   const float* __restrict__ w_eta2,
                   const float* __restrict__ b_eta2,
                   float* __restrict__ out) {
    // Staged row segment, padded: logical slot t -> phys t + (t>>2).
    // Thread chunk reads hit phys = tid*5 + k  => lane stride 80B, conflict-free.
    __shared__ float4 s_data[SMEM_F4];
    __shared__ float4 s_woff[NWARPS];
    __shared__ float4 s_total;
    __shared__ float  s_soc;

    const int row  = blockIdx.x;
    const int tid  = threadIdx.x;
    const int lane = tid & 31;
    const int warp = tid >> 5;

    const float4* __restrict__ Xr = reinterpret_cast<const float4*>(X) + (size_t)row * L_LEN;
    float4* __restrict__ Or       = reinterpret_cast<float4*>(out)     + (size_t)row * L_LEN;

    // Per-row scalars: SC = [Q, eta0, R, cap]
    const float Q    = SC[row * 4 + 0];
    const float eta0 = SC[row * 4 + 1];
    const float R    = SC[row * 4 + 2];
    const float cap  = SC[row * 4 + 3];

    const float we0 = w_eta1[0];
    const float we1 = w_eta1[1];
    const float be1 = b_eta1[0];
    const float we2 = w_eta2[0];
    const float be2 = b_eta2[0];

    const float dscale = eta0 / (3600.0f * Q);

    float cx = 0.f, cy = 0.f, cz = 0.f, cw = 0.f;  // cross-round carry

    #pragma unroll 1
    for (int r = 0; r < ROUNDS; ++r) {
        const int tbase = r * SEG;

        // ---- Phase 1: coalesced load, compute delta_eta, stage as (de,I,T,U) ----
        #pragma unroll
        for (int j = 0; j < CHUNK; ++j) {
            const int tl = j * TPB + tid;          // local timestep in segment
            float4 x = Xr[tbase + tl];
            const float de = we2 * softplus_f(we0 * x.y + we1 * x.z + be1) + be2;
            if (r == 0 && j == 0 && tid == 0) {
                // soc_init from element 0 (x here IS element 0)
                float z = w_init1[0] * x.y + w_init1[1] * x.z
                        + w_init1[2] * x.w + w_init1[3] * R + b_init1[0];
                s_soc = cap * (1.0f + (w_init2[0] * softplus_f(z) + b_init2[0]));
            }
            s_data[tl + (tl >> 2)] = make_float4(de, x.y, x.z, x.w);
        }
        __syncthreads();                           // barrier A

        // Boundary neighbor for the last thread (element tbase+SEG)
        float4 nbr = make_float4(0.f, 0.f, 0.f, 0.f);
        if (tid == TPB - 1 && r < ROUNDS - 1) {
            float4 xn = Xr[tbase + SEG];
            const float den = we2 * softplus_f(we0 * xn.y + we1 * xn.z + be1) + be2;
            nbr = make_float4(den, xn.y, xn.z, xn.w);
        }

        // ---- Phase 2: per-thread serial exclusive prefixes over CHUNK incs ----
        const int c0 = tid * (CHUNK + 1);          // phys base (= PHYS(tid*CHUNK))
        float4 cur = s_data[c0];
        float4 pre[CHUNK];
        float tx = 0.f, ty = 0.f, tz = 0.f, tw = 0.f;
        #pragma unroll
        for (int k = 0; k < CHUNK; ++k) {
            float4 nxt;
            if (k < CHUNK - 1)            nxt = s_data[c0 + k + 1];
            else if (tid < TPB - 1)       nxt = s_data[c0 + CHUNK + 1]; // next thread's first
            else                          nxt = nbr;
            pre[k] = make_float4(tx, ty, tz, tw);
            const bool last_elem = (r == ROUNDS - 1) && (tid == TPB - 1) && (k == CHUNK - 1);
            if (!last_elem) {
                const float dy = dscale * (1.0f + cur.x) * cur.y;
                tx += dy * (nxt.y - cur.y);   // I channel
                ty += dy * (nxt.z - cur.z);   // T channel
                tz += dy * (nxt.w - cur.w);   // U channel
                tw += dy * (nxt.x - cur.x);   // delta_eta channel
            }
            cur = nxt;
        }

        // ---- Phase 3: block exclusive scan of thread totals (once per SEG) ----
        float sx = tx, sy = ty, sz = tz, sw = tw;
        #pragma unroll
        for (int d = 1; d < 32; d <<= 1) {
            float ax = __shfl_up_sync(0xFFFFFFFFu, sx, d);
            float ay = __shfl_up_sync(0xFFFFFFFFu, sy, d);
            float az = __shfl_up_sync(0xFFFFFFFFu, sz, d);
            float aw = __shfl_up_sync(0xFFFFFFFFu, sw, d);
            if (lane >= d) { sx += ax; sy += ay; sz += az; sw += aw; }
        }
        if (lane == 31) s_woff[warp] = make_float4(sx, sy, sz, sw);
        __syncthreads();                           // barrier B

        if (warp == 0) {
            float4 v = (lane < NWARPS) ? s_woff[lane]
                                       : make_float4(0.f, 0.f, 0.f, 0.f);
            #pragma unroll
            for (int d = 1; d < NWARPS; d <<= 1) {
                float ax = __shfl_up_sync(0xFFFFFFFFu, v.x, d);
                float ay = __shfl_up_sync(0xFFFFFFFFu, v.y, d);
                float az = __shfl_up_sync(0xFFFFFFFFu, v.z, d);
                float aw = __shfl_up_sync(0xFFFFFFFFu, v.w, d);
                if (lane >= d) { v.x += ax; v.y += ay; v.z += az; v.w += aw; }
            }
            float4 e;
            e.x = __shfl_up_sync(0xFFFFFFFFu, v.x, 1);
            e.y = __shfl_up_sync(0xFFFFFFFFu, v.y, 1);
            e.z = __shfl_up_sync(0xFFFFFFFFu, v.z, 1);
            e.w = __shfl_up_sync(0xFFFFFFFFu, v.w, 1);
            if (lane == 0) e = make_float4(0.f, 0.f, 0.f, 0.f);
            if (lane == NWARPS - 1) s_total = v;
            if (lane < NWARPS) s_woff[lane] = e;
        }
        __syncthreads();                           // barrier C

        const float4 wb = s_woff[warp];
        float ex = __shfl_up_sync(0xFFFFFFFFu, sx, 1);
        float ey = __shfl_up_sync(0xFFFFFFFFu, sy, 1);
        float ez = __shfl_up_sync(0xFFFFFFFFu, sz, 1);
        float ew = __shfl_up_sync(0xFFFFFFFFu, sw, 1);
        if (lane == 0) { ex = ey = ez = ew = 0.f; }

        const float soc = s_soc;
        const float bx = soc + cx + wb.x + ex;
        const float by = soc + cy + wb.y + ey;
        const float bz = soc + cz + wb.z + ez;
        const float bw = soc + cw + wb.w + ew;

        // ---- Phase 4: write outputs back into smem (conflict-free) ----
        #pragma unroll
        for (int k = 0; k < CHUNK; ++k) {
            s_data[c0 + k] = make_float4(bx + pre[k].x, by + pre[k].y,
                                         bz + pre[k].z, bw + pre[k].w);
        }
        __syncthreads();                           // barrier D

        // ---- Phase 5: coalesced store ----
        #pragma unroll
        for (int j = 0; j < CHUNK; ++j) {
            const int tl = j * TPB + tid;
            Or[tbase + tl] = s_data[tl + (tl >> 2)];
        }

        const float4 bt = s_total;
        cx += bt.x; cy += bt.y; cz += bt.z; cw += bt.w;

        if (r < ROUNDS - 1) __syncthreads();       // barrier E: protect smem reuse
    }
}

extern "C" void kernel_launch(void* const* d_in, const int* in_sizes, int n_in,
                              void* d_out, int out_size) {
    const float* X       = (const float*)d_in[0];
    const float* SC      = (const float*)d_in[1];
    const float* w_init1 = (const float*)d_in[2];
    const float* b_init1 = (const float*)d_in[3];
    const float* w_init2 = (const float*)d_in[4];
    const float* b_init2 = (const float*)d_in[5];
    const float* w_eta1  = (const float*)d_in[6];
    const float* b_eta1  = (const float*)d_in[7];
    const float* w_eta2  = (const float*)d_in[8];
    const float* b_eta2  = (const float*)d_in[9];
    float* out = (float*)d_out;

    socnet_kernel<<<N_ROWS, TPB>>>(X, SC,
                                   w_init1, b_init1, w_init2, b_init2,
                                   w_eta1, b_eta1, w_eta2, b_eta2,
                                   out);
}

// round 4
// speedup vs baseline: 1.7813x; 1.0339x over previous
#include <cuda_runtime.h>

#define L_LEN   4096
#define N_ROWS  4096
#define TILES   (L_LEN / 32)      // 128 tiles of 32 float4 per row
#define TPB     128
#define WPC     (TPB / 32)        // 4 rows per CTA
#define FULLM   0xFFFFFFFFu

// Fast, numerically safe softplus: max(x,0) + log(1 + e^{-|x|})
__device__ __forceinline__ float softplus_f(float x) {
    return fmaxf(x, 0.0f) + __logf(1.0f + __expf(-fabsf(x)));
}

__global__ __launch_bounds__(TPB)
void socnet_kernel(const float* __restrict__ X,
                   const float* __restrict__ SC,
                   const float* __restrict__ w_init1,
                   const float* __restrict__ b_init1,
                   const float* __restrict__ w_init2,
                   const float* __restrict__ b_init2,
                   const float* __restrict__ w_eta1,
                   const float* __restrict__ b_eta1,
                   const float* __restrict__ w_eta2,
                   const float* __restrict__ b_eta2,
                   float* __restrict__ out) {
    const int lane = threadIdx.x & 31;
    const int row  = blockIdx.x * WPC + (threadIdx.x >> 5);

    const float4* __restrict__ Xr = reinterpret_cast<const float4*>(X) + (size_t)row * L_LEN;
    float4* __restrict__ Or       = reinterpret_cast<float4*>(out)     + (size_t)row * L_LEN;

    // Per-row scalars: SC = [Q, eta0, R, cap]
    const float Q    = SC[row * 4 + 0];
    const float eta0 = SC[row * 4 + 1];
    const float R    = SC[row * 4 + 2];
    const float cap  = SC[row * 4 + 3];

    const float we0 = w_eta1[0];
    const float we1 = w_eta1[1];
    const float be1 = b_eta1[0];
    const float we2 = w_eta2[0];
    const float be2 = b_eta2[0];

    const float dscale = eta0 / (3600.0f * Q);

    // ---- Tile 0 load + per-element delta_eta ----
    float4 x0 = Xr[lane];
    float pI = x0.y, pT = x0.z, pU = x0.w;
    float pde = we2 * softplus_f(we0 * pI + we1 * pT + be1) + be2;

    // ---- soc_init (uniform across warp, from element 0) ----
    const float I0 = __shfl_sync(FULLM, pI, 0);
    const float T0 = __shfl_sync(FULLM, pT, 0);
    const float U0 = __shfl_sync(FULLM, pU, 0);
    float z = w_init1[0] * I0 + w_init1[1] * T0
            + w_init1[2] * U0 + w_init1[3] * R + b_init1[0];
    const float soc = cap * (1.0f + (w_init2[0] * softplus_f(z) + b_init2[0]));

    // Running base = soc + prefix of all earlier tiles' increments
    float bx = soc, by = soc, bz = soc, bw = soc;

    #pragma unroll 2
    for (int it = 0; it < TILES; ++it) {
        // Pipeline: load next tile and its delta_eta
        float nI, nT, nU, nde;
        if (it < TILES - 1) {
            float4 xn = Xr[(it + 1) * 32 + lane];
            nI = xn.y; nT = xn.z; nU = xn.w;
            nde = we2 * softplus_f(we0 * nI + we1 * nT + be1) + be2;
        } else {
            nI = pI; nT = pT; nU = pU; nde = pde;
        }

        // Neighbor value at t+1: rotate-by-1 shfl; lane 0 contributes next tile's
        // first element so lane 31 receives it.
        const int src = (lane + 1) & 31;
        const float qI  = __shfl_sync(FULLM, (lane == 0) ? nI  : pI,  src);
        const float qT  = __shfl_sync(FULLM, (lane == 0) ? nT  : pT,  src);
        const float qU  = __shfl_sync(FULLM, (lane == 0) ? nU  : pU,  src);
        const float qde = __shfl_sync(FULLM, (lane == 0) ? nde : pde, src);

        const float dy = dscale * (1.0f + pde) * pI;
        float ex = dy * (qI - pI);
        float ey = dy * (qT - pT);
        float ez = dy * (qU - pU);
        float ew = dy * (qde - pde);
        if (it == TILES - 1 && lane == 31) {  // inc[L-1] does not exist
            ex = 0.f; ey = 0.f; ez = 0.f; ew = 0.f;
        }

        // Warp-inclusive scan of the 4 channels
        float sx = ex, sy = ey, sz = ez, sw = ew;
        #pragma unroll
        for (int d = 1; d < 32; d <<= 1) {
            float ax = __shfl_up_sync(FULLM, sx, d);
            float ay = __shfl_up_sync(FULLM, sy, d);
            float az = __shfl_up_sync(FULLM, sz, d);
            float aw = __shfl_up_sync(FULLM, sw, d);
            if (lane >= d) { sx += ax; sy += ay; sz += az; sw += aw; }
        }

        // out[t] = base + exclusive prefix = base + (S - e)
        float4 o;
        o.x = bx + (sx - ex);
        o.y = by + (sy - ey);
        o.z = bz + (sz - ez);
        o.w = bw + (sw - ew);
        Or[it * 32 + lane] = o;

        // Carry the tile total forward
        bx += __shfl_sync(FULLM, sx, 31);
        by += __shfl_sync(FULLM, sy, 31);
        bz += __shfl_sync(FULLM, sz, 31);
        bw += __shfl_sync(FULLM, sw, 31);

        pI = nI; pT = nT; pU = nU; pde = nde;
    }
}

extern "C" void kernel_launch(void* const* d_in, const int* in_sizes, int n_in,
                              void* d_out, int out_size) {
    const float* X       = (const float*)d_in[0];
    const float* SC      = (const float*)d_in[1];
    const float* w_init1 = (const float*)d_in[2];
    const float* b_init1 = (const float*)d_in[3];
    const float* w_init2 = (const float*)d_in[4];
    const float* b_init2 = (const float*)d_in[5];
    const float* w_eta1  = (const float*)d_in[6];
    const float* b_eta1  = (const float*)d_in[7];
    const float* w_eta2  = (const float*)d_in[8];
    const float* b_eta2  = (const float*)d_in[9];
    float* out = (float*)d_out;

    socnet_kernel<<<N_ROWS / WPC, TPB>>>(X, SC,
                                         w_init1, b_init1, w_init2, b_init2,
                                         w_eta1, b_eta1, w_eta2, b_eta2,
                                         out);
}